// round 9
// baseline (speedup 1.0000x reference)
#include <cuda_runtime.h>

// SPDUnVectorize: x[B, L] packed upper triangle (row-major, incl. diag) ->
// out[B, n, n] symmetric. B=1024, n=256, L=n(n+1)/2=32896.
//
// One block = one 32x32 tile x 4 batches as two double-buffered pairs.
// Each __syncthreads() has the other pair's 8 LDG/thread in flight behind it.

#define NMAT   256
#define L_IN   32896
#define BATCH  1024
#define TILE   32
#define NTROW  8
#define NTILES 36
#define PAD    33

__device__ __forceinline__ int tri_off(int r) {
    return r * NMAT - (r * (r - 1)) / 2;
}

__global__ __launch_bounds__(256, 7)
void spd_unvec_kernel(const float* __restrict__ in, float* __restrict__ out) {
    __shared__ float sA0[TILE][PAD], sA1[TILE][PAD];
    __shared__ float sB0[TILE][PAD], sB1[TILE][PAD];

    const int b0 = blockIdx.y * 4;
    int t = blockIdx.x;

    int ti = 0;
    int rem = NTROW;
    while (t >= rem) { t -= rem; rem--; ti++; }
    const int tj = ti + t;

    const int lane = threadIdx.x & 31;   // column within tile (loads/upper)
    const int wy   = threadIdx.x >> 5;   // base row
    const int row  = threadIdx.x >> 3;   // row (mirror stores)
    const int qc   = (threadIdx.x & 7) << 2;

    const float* __restrict__ i0 = in + (size_t)(b0 + 0) * L_IN;
    const float* __restrict__ i1 = in + (size_t)(b0 + 1) * L_IN;
    const float* __restrict__ i2 = in + (size_t)(b0 + 2) * L_IN;
    const float* __restrict__ i3 = in + (size_t)(b0 + 3) * L_IN;
    float* __restrict__ o0 = out + (size_t)(b0 + 0) * (NMAT * NMAT);
    float* __restrict__ o1 = out + (size_t)(b0 + 1) * (NMAT * NMAT);
    float* __restrict__ o2 = out + (size_t)(b0 + 2) * (NMAT * NMAT);
    float* __restrict__ o3 = out + (size_t)(b0 + 3) * (NMAT * NMAT);

    if (ti == tj) {
        const int R = ti * TILE;
        // ---- Diagonal tile: pair A load, pair B load issued, then syncs ----
        #pragma unroll
        for (int k = 0; k < 4; k++) {
            const int lr = wy + k * 8;
            if (lane >= lr) {
                const int idx = tri_off(R + lr) + lane - lr;
                sA0[lr][lane] = i0[idx];
                sA1[lr][lane] = i1[idx];
                sB0[lr][lane] = i2[idx];
                sB1[lr][lane] = i3[idx];
            }
        }
        __syncthreads();
        const int r = R + row;
        float4 v0, v1, v2, v3;
        #pragma unroll
        for (int k = 0; k < 4; k++) {
            const int c  = qc + k;
            const bool up = (c >= row);
            ((float*)&v0)[k] = up ? sA0[row][c] : sA0[c][row];
            ((float*)&v1)[k] = up ? sA1[row][c] : sA1[c][row];
            ((float*)&v2)[k] = up ? sB0[row][c] : sB0[c][row];
            ((float*)&v3)[k] = up ? sB1[row][c] : sB1[c][row];
        }
        *reinterpret_cast<float4*>(&o0[r * NMAT + R + qc]) = v0;
        *reinterpret_cast<float4*>(&o1[r * NMAT + R + qc]) = v1;
        *reinterpret_cast<float4*>(&o2[r * NMAT + R + qc]) = v2;
        *reinterpret_cast<float4*>(&o3[r * NMAT + R + qc]) = v3;
    } else {
        // ---- Off-diagonal tile (ti < tj), pipelined pairs ----
        const int cb = tj * TILE + lane;     // global col for loads/upper
        int idxk[4];
        #pragma unroll
        for (int k = 0; k < 4; k++) {
            const int r = ti * TILE + wy + k * 8;
            idxk[k] = tri_off(r) - r + cb;
        }

        // Pair A: load, store upper direct, stage to smem.
        float a0[4], a1[4];
        #pragma unroll
        for (int k = 0; k < 4; k++) { a0[k] = i0[idxk[k]]; a1[k] = i1[idxk[k]]; }
        #pragma unroll
        for (int k = 0; k < 4; k++) {
            const int lr = wy + k * 8;
            const int r  = ti * TILE + lr;
            o0[r * NMAT + cb] = a0[k];
            o1[r * NMAT + cb] = a1[k];
            sA0[lr][lane] = a0[k];
            sA1[lr][lane] = a1[k];
        }

        // Pair B: issue loads NOW (in flight across syncA + mirrorA).
        float c0[4], c1[4];
        #pragma unroll
        for (int k = 0; k < 4; k++) { c0[k] = i2[idxk[k]]; c1[k] = i3[idxk[k]]; }

        __syncthreads();   // A staged; B's LDGs outstanding underneath

        // Mirror A: transposed smem read -> STG.128.
        const int r2 = tj * TILE + row;
        float4 m0, m1;
        #pragma unroll
        for (int k = 0; k < 4; k++) {
            const int c = qc + k;
            ((float*)&m0)[k] = sA0[c][row];
            ((float*)&m1)[k] = sA1[c][row];
        }
        *reinterpret_cast<float4*>(&o0[r2 * NMAT + ti * TILE + qc]) = m0;
        *reinterpret_cast<float4*>(&o1[r2 * NMAT + ti * TILE + qc]) = m1;

        // Pair B: store upper direct, stage to smem.
        #pragma unroll
        for (int k = 0; k < 4; k++) {
            const int lr = wy + k * 8;
            const int r  = ti * TILE + lr;
            o2[r * NMAT + cb] = c0[k];
            o3[r * NMAT + cb] = c1[k];
            sB0[lr][lane] = c0[k];
            sB1[lr][lane] = c1[k];
        }
        __syncthreads();

        // Mirror B.
        float4 m2, m3;
        #pragma unroll
        for (int k = 0; k < 4; k++) {
            const int c = qc + k;
            ((float*)&m2)[k] = sB0[c][row];
            ((float*)&m3)[k] = sB1[c][row];
        }
        *reinterpret_cast<float4*>(&o2[r2 * NMAT + ti * TILE + qc]) = m2;
        *reinterpret_cast<float4*>(&o3[r2 * NMAT + ti * TILE + qc]) = m3;
    }
}

extern "C" void kernel_launch(void* const* d_in, const int* in_sizes, int n_in,
                              void* d_out, int out_size) {
    const float* in = (const float*)d_in[0];
    float* out = (float*)d_out;
    dim3 grid(NTILES, BATCH / 4);
    dim3 block(256);
    spd_unvec_kernel<<<grid, block>>>(in, out);
}

// round 10
// speedup vs baseline: 1.0341x; 1.0341x over previous
#include <cuda_runtime.h>
#include <cstdint>

// SPDUnVectorize: x[B, L] packed upper triangle (row-major, incl. diag) ->
// out[B, n, n] symmetric. B=1024, n=256, L=n(n+1)/2=32896.
//
// R8 skeleton (one block = one 32x32 tile x 2 batches, early register-direct
// upper stores) + 256-bit mirror stores (st.global.v8.b32, sm_100+).

#define NMAT   256
#define L_IN   32896
#define BATCH  1024
#define TILE   32
#define NTROW  8
#define NTILES 36
#define PAD    33

__device__ __forceinline__ int tri_off(int r) {
    return r * NMAT - (r * (r - 1)) / 2;
}

__device__ __forceinline__ void stg256(float* p, const float* v) {
    asm volatile(
        "st.global.v8.b32 [%0], {%1, %2, %3, %4, %5, %6, %7, %8};"
        :: "l"(p),
           "r"(__float_as_uint(v[0])), "r"(__float_as_uint(v[1])),
           "r"(__float_as_uint(v[2])), "r"(__float_as_uint(v[3])),
           "r"(__float_as_uint(v[4])), "r"(__float_as_uint(v[5])),
           "r"(__float_as_uint(v[6])), "r"(__float_as_uint(v[7]))
        : "memory");
}

__global__ __launch_bounds__(256, 7)
void spd_unvec_kernel(const float* __restrict__ in, float* __restrict__ out) {
    __shared__ float s0[TILE][PAD];
    __shared__ float s1[TILE][PAD];

    const int b0 = blockIdx.y * 2;
    int t = blockIdx.x;

    int ti = 0;
    int rem = NTROW;
    while (t >= rem) { t -= rem; rem--; ti++; }
    const int tj = ti + t;

    const int lane = threadIdx.x & 31;   // column within tile (loads/upper)
    const int wy   = threadIdx.x >> 5;   // 0..7 (base row)

    const float* __restrict__ in0  = in  + (size_t)b0 * L_IN;
    const float* __restrict__ in1  = in0 + L_IN;
    float*       __restrict__ out0 = out + (size_t)b0 * (NMAT * NMAT);
    float*       __restrict__ out1 = out0 + (NMAT * NMAT);

    if (ti == tj) {
        // ---- Diagonal tile, both batches (8/36 tiles) ----
        #pragma unroll
        for (int k = 0; k < 4; k++) {
            const int lr = wy + k * 8;
            const int r  = ti * TILE + lr;
            if (lane >= lr) {
                const int idx = tri_off(r) + lane - lr;
                s0[lr][lane] = in0[idx];
                s1[lr][lane] = in1[idx];
            }
        }
        __syncthreads();
        const int row = threadIdx.x >> 3;
        const int qc  = (threadIdx.x & 7) << 2;
        const int r   = ti * TILE + row;
        float4 v0, v1;
        #pragma unroll
        for (int k = 0; k < 4; k++) {
            const int c  = qc + k;
            const bool up = (c >= row);
            ((float*)&v0)[k] = up ? s0[row][c] : s0[c][row];
            ((float*)&v1)[k] = up ? s1[row][c] : s1[c][row];
        }
        *reinterpret_cast<float4*>(&out0[r * NMAT + ti * TILE + qc]) = v0;
        *reinterpret_cast<float4*>(&out1[r * NMAT + ti * TILE + qc]) = v1;
    } else {
        // ---- Off-diagonal tile (ti < tj), both batches ----
        // Stage all 8 loads (4 rows x 2 batches) in registers first.
        float v0[4], v1[4];
        #pragma unroll
        for (int k = 0; k < 4; k++) {
            const int lr  = wy + k * 8;
            const int r   = ti * TILE + lr;
            const int idx = tri_off(r) - r + tj * TILE + lane;
            v0[k] = in0[idx];
            v1[k] = in1[idx];
        }
        // Upper tile: store DIRECTLY from registers before the barrier.
        #pragma unroll
        for (int k = 0; k < 4; k++) {
            const int lr = wy + k * 8;
            const int r  = ti * TILE + lr;
            out0[r * NMAT + tj * TILE + lane] = v0[k];
            out1[r * NMAT + tj * TILE + lane] = v1[k];
            s0[lr][lane] = v0[k];
            s1[lr][lane] = v1[k];
        }
        __syncthreads();

        // Mirror tile: one 256-bit store per thread.
        // tid -> (batch, row, 8-float chunk): 256 threads = 2 batches x 32
        // rows x 4 chunks. Smem banks (c+row) mod 32: conflict-free.
        const int mb   = threadIdx.x >> 7;           // 0..1 batch
        const int mrow = (threadIdx.x >> 2) & 31;    // 0..31 mirror row
        const int moc  = (threadIdx.x & 3) << 3;     // 0,8,16,24

        float m[8];
        if (mb == 0) {
            #pragma unroll
            for (int k = 0; k < 8; k++) m[k] = s0[moc + k][mrow];
            stg256(&out0[(tj * TILE + mrow) * NMAT + ti * TILE + moc], m);
        } else {
            #pragma unroll
            for (int k = 0; k < 8; k++) m[k] = s1[moc + k][mrow];
            stg256(&out1[(tj * TILE + mrow) * NMAT + ti * TILE + moc], m);
        }
    }
}

extern "C" void kernel_launch(void* const* d_in, const int* in_sizes, int n_in,
                              void* d_out, int out_size) {
    const float* in = (const float*)d_in[0];
    float* out = (float*)d_out;
    dim3 grid(NTILES, BATCH / 2);
    dim3 block(256);
    spd_unvec_kernel<<<grid, block>>>(in, out);
}